// round 1
// baseline (speedup 1.0000x reference)
#include <cuda_runtime.h>

#define NTT 365
#define NGRID 2048
#define NX 16
#define NH 256
#define NG (4*NH)      /* 1024 */
#define KTOT (2*NH)    /* 512  */
#define CELLS 16
#define ROWS (NTT*NGRID)

typedef unsigned long long ull;

// Scratch (static device globals — allocation at module load, per harness rules)
__device__ float g_x0[(size_t)ROWS * NH];   // 765 MB: relu(x @ w_in^T + b_in)
__device__ float g_wT[KTOT * NG];           // 2 MB: [k][g], k<256 -> w_ih, else w_hh
__device__ float g_bias2[NG];               // b_ih + b_hh

// ---------------------------------------------------------------------------
// Kernel 0: transpose/concat weights + fold biases
// ---------------------------------------------------------------------------
__global__ void prep_kernel(const float* __restrict__ w_ih, const float* __restrict__ w_hh,
                            const float* __restrict__ b_ih, const float* __restrict__ b_hh) {
    int idx = blockIdx.x * blockDim.x + threadIdx.x;
    if (idx < KTOT * NG) {
        int k = idx / NG, g = idx % NG;
        g_wT[idx] = (k < NH) ? w_ih[g * NH + k] : w_hh[g * NH + (k - NH)];
    }
    if (idx < NG) g_bias2[idx] = b_ih[idx] + b_hh[idx];
}

// ---------------------------------------------------------------------------
// Kernel 1: x0 = relu(x @ w_in^T + b_in)   [ROWS, NH]
// ---------------------------------------------------------------------------
__global__ void __launch_bounds__(256) input_kernel(const float* __restrict__ x,
                                                    const float* __restrict__ w_in,
                                                    const float* __restrict__ b_in) {
    __shared__ float w_s[NH][NX + 1];   // +1 pad: conflict-free per-h access
    __shared__ float xt[16][NX];
    int tid = threadIdx.x;
    size_t r0 = (size_t)blockIdx.x * 16;
#pragma unroll
    for (int i = 0; i < NX; i++) w_s[tid][i] = w_in[tid * NX + i];
    xt[tid >> 4][tid & 15] = x[r0 * NX + tid];
    __syncthreads();
    float b = b_in[tid];
    for (int r = 0; r < 16; r++) {
        float acc = b;
#pragma unroll
        for (int i = 0; i < NX; i++) acc += xt[r][i] * w_s[tid][i];
        g_x0[(r0 + r) * NH + tid] = fmaxf(acc, 0.f);
    }
}

// ---------------------------------------------------------------------------
// Kernel 2: fused recurrent scan. 128 blocks x 16 cells, thread j owns hidden j.
// gates[m][g] = bias2[g] + sum_k sb[k][m] * wT[k][g],  sb = [x0_t | h]
// ---------------------------------------------------------------------------
__device__ __forceinline__ ull pk2(float w) {
    ull r; asm("mov.b64 %0, {%1,%1};" : "=l"(r) : "f"(w)); return r;
}
__device__ __forceinline__ ull fma2(ull a, ull b, ull c) {
    ull d; asm("fma.rn.f32x2 %0, %1, %2, %3;" : "=l"(d) : "l"(a), "l"(b), "l"(c)); return d;
}
__device__ __forceinline__ float2 unpk(ull v) {
    float2 r; asm("mov.b64 {%0, %1}, %2;" : "=f"(r.x), "=f"(r.y) : "l"(v)); return r;
}
__device__ __forceinline__ float sigmoidf_(float x) { return 1.f / (1.f + expf(-x)); }

__global__ void __launch_bounds__(256, 1) lstm_kernel(const float* __restrict__ w_out,
                                                      const float* __restrict__ b_out,
                                                      float* __restrict__ out) {
    __shared__ float sb[KTOT * CELLS];   // [k][m], m fastest; rows<256: x0_t, rows>=256: h
    __shared__ float redsm[8][CELLS];
    int tid  = threadIdx.x;
    int lane = tid & 31, warp = tid >> 5;
    int b0   = blockIdx.x * CELLS;

    float cst[CELLS], hv[CELLS];
#pragma unroll
    for (int m = 0; m < CELLS; m++) { cst[m] = 0.f; sb[(NH + tid) * CELLS + m] = 0.f; }

    float bi = g_bias2[tid], bf = g_bias2[tid + NH];
    float bg = g_bias2[tid + 2 * NH], bo = g_bias2[tid + 3 * NH];
    float wo_j = w_out[tid];
    float bout = b_out[0];

    for (int t = 0; t < NTT; t++) {
        // stage x0_t (rows < 256 of sb); h rows written at end of previous iter
        const float* xp = g_x0 + ((size_t)t * NGRID + b0) * NH;
#pragma unroll
        for (int r = 0; r < CELLS; r++) sb[tid * CELLS + r] = xp[r * NH + tid];
        __syncthreads();

        ull ai[8], af[8], ag[8], ao[8];
#pragma unroll
        for (int m2 = 0; m2 < 8; m2++) {
            ai[m2] = pk2(bi); af[m2] = pk2(bf); ag[m2] = pk2(bg); ao[m2] = pk2(bo);
        }

        const float* wp = g_wT + tid;
#pragma unroll 4
        for (int k = 0; k < KTOT; k++) {
            float wi = wp[k * NG];
            float wf = wp[k * NG + NH];
            float wg = wp[k * NG + 2 * NH];
            float wo = wp[k * NG + 3 * NH];
            ull di = pk2(wi), df = pk2(wf), dg = pk2(wg), d_o = pk2(wo);
            const ull* s2 = reinterpret_cast<const ull*>(sb + k * CELLS);
#pragma unroll
            for (int m2 = 0; m2 < 8; m2++) {
                ull s = s2[m2];                   // broadcast LDS.64 (pair of cells)
                ai[m2] = fma2(di,  s, ai[m2]);
                af[m2] = fma2(df,  s, af[m2]);
                ag[m2] = fma2(dg,  s, ag[m2]);
                ao[m2] = fma2(d_o, s, ao[m2]);
            }
        }

        // pointwise LSTM cell, fully in registers
        float p[CELLS];
#pragma unroll
        for (int m2 = 0; m2 < 8; m2++) {
            float2 vi = unpk(ai[m2]), vf = unpk(af[m2]);
            float2 vg = unpk(ag[m2]), vo = unpk(ao[m2]);
            {
                int m = 2 * m2;
                float i = sigmoidf_(vi.x), f = sigmoidf_(vf.x);
                float g = tanhf(vg.x),     o = sigmoidf_(vo.x);
                cst[m] = f * cst[m] + i * g;
                float h = o * tanhf(cst[m]);
                hv[m] = h; p[m] = h * wo_j;
            }
            {
                int m = 2 * m2 + 1;
                float i = sigmoidf_(vi.y), f = sigmoidf_(vf.y);
                float g = tanhf(vg.y),     o = sigmoidf_(vo.y);
                cst[m] = f * cst[m] + i * g;
                float h = o * tanhf(cst[m]);
                hv[m] = h; p[m] = h * wo_j;
            }
        }

        // fused linearOut (NY=1): reduce h*w_out over hidden dim
#pragma unroll
        for (int m = 0; m < CELLS; m++) {
            float v = p[m];
            v += __shfl_down_sync(0xffffffffu, v, 16);
            v += __shfl_down_sync(0xffffffffu, v, 8);
            v += __shfl_down_sync(0xffffffffu, v, 4);
            v += __shfl_down_sync(0xffffffffu, v, 2);
            v += __shfl_down_sync(0xffffffffu, v, 1);
            if (lane == 0) redsm[warp][m] = v;
        }
        __syncthreads();   // all sb reads done + redsm visible

        if (tid < CELLS) {
            float s = bout;
#pragma unroll
            for (int w = 0; w < 8; w++) s += redsm[w][tid];
            out[(size_t)t * NGRID + b0 + tid] = s;
        }
        // publish new h (rows >= 256; disjoint from next iter's x0 staging)
#pragma unroll
        for (int m = 0; m < CELLS; m++) sb[(NH + tid) * CELLS + m] = hv[m];
    }
}

// ---------------------------------------------------------------------------
extern "C" void kernel_launch(void* const* d_in, const int* in_sizes, int n_in,
                              void* d_out, int out_size) {
    const float* x     = (const float*)d_in[0];
    const float* w_in  = (const float*)d_in[1];
    const float* b_in  = (const float*)d_in[2];
    const float* w_ih  = (const float*)d_in[3];
    const float* w_hh  = (const float*)d_in[4];
    const float* b_ih  = (const float*)d_in[5];
    const float* b_hh  = (const float*)d_in[6];
    const float* w_out = (const float*)d_in[7];
    const float* b_out = (const float*)d_in[8];
    float* out = (float*)d_out;

    prep_kernel<<<(KTOT * NG + 255) / 256, 256>>>(w_ih, w_hh, b_ih, b_hh);
    input_kernel<<<ROWS / 16, 256>>>(x, w_in, b_in);
    lstm_kernel<<<NGRID / CELLS, 256>>>(w_out, b_out, out);
}

// round 5
// speedup vs baseline: 2.9674x; 2.9674x over previous
#include <cuda_runtime.h>
#include <cuda_bf16.h>
#include <cstdint>

#define NTT   365
#define NGRID 2048
#define NX    16
#define NH    256
#define NG    1024
#define CELLS 16
#define NBLK  (NGRID/CELLS)    /* 128 */
#define TC    73               /* chunk timesteps; 5*73 = 365 */
#define NCH   5
#define CROWS (TC*NGRID)       /* 149504 rows per chunk */

// ---------------------------------------------------------------------------
// Device-global scratch (total ~1.4 GB — must stay < 2 GB for host link)
// ---------------------------------------------------------------------------
__device__ float g_x0[(size_t)NTT * NGRID * NH];      // 765 MB fp32 relu(x@w_in^T+b)
__device__ float g_xg[(size_t)CROWS * NG];            // 612 MB per-chunk xg
__device__ uint4 g_qih[NG * 16 * 4];                  // packed w_ih frag records (1MB)
__device__ uint4 g_qhh[NG * 16 * 4];                  // packed w_hh frag records (1MB)
__device__ float g_bias2[NG];
__device__ float g_cs[NBLK * 256 * 16];               // c-state spill (2MB)
#define HSB (16 * 528)                                /* one h split tile: 8448 B */
__device__ uint32_t g_hs[NBLK * (2 * HSB / 4)];       // h-state spill (2.2MB)

// ---------------------------------------------------------------------------
// PTX helpers (sm_100 baseline-safe: mma.sync / ldmatrix / cp.async only)
// ---------------------------------------------------------------------------
__device__ __forceinline__ uint32_t su32(const void* p) {
    uint32_t a;
    asm("{ .reg .u64 t; cvta.to.shared.u64 t, %1; cvt.u32.u64 %0, t; }" : "=r"(a) : "l"(p));
    return a;
}
__device__ __forceinline__ void mma_bf16(float& c0, float& c1, float& c2, float& c3,
                                         uint32_t a0, uint32_t a1, uint32_t a2, uint32_t a3,
                                         uint32_t b0, uint32_t b1) {
    asm volatile(
        "mma.sync.aligned.m16n8k16.row.col.f32.bf16.bf16.f32 "
        "{%0,%1,%2,%3},{%4,%5,%6,%7},{%8,%9},{%0,%1,%2,%3};"
        : "+f"(c0), "+f"(c1), "+f"(c2), "+f"(c3)
        : "r"(a0), "r"(a1), "r"(a2), "r"(a3), "r"(b0), "r"(b1));
}
__device__ __forceinline__ void ldmat4(uint32_t* r, uint32_t addr) {
    asm volatile("ldmatrix.sync.aligned.m8n8.x4.shared.b16 {%0,%1,%2,%3},[%4];"
                 : "=r"(r[0]), "=r"(r[1]), "=r"(r[2]), "=r"(r[3]) : "r"(addr));
}
__device__ __forceinline__ void cpa16(uint32_t s, const void* g) {
    asm volatile("cp.async.cg.shared.global [%0],[%1],16;" :: "r"(s), "l"(g));
}
#define CPA_COMMIT() asm volatile("cp.async.commit_group;" ::: "memory")
#define CPA_WAIT0()  asm volatile("cp.async.wait_group 0;" ::: "memory")

__device__ __forceinline__ uint32_t pk2bf(float lo, float hi) {
    uint32_t l = (uint32_t)__bfloat16_as_ushort(__float2bfloat16(lo));
    uint32_t h = (uint32_t)__bfloat16_as_ushort(__float2bfloat16(hi));
    return l | (h << 16);
}
__device__ __forceinline__ void split2(float v, float& s0f, float& s1f) {
    __nv_bfloat16 h0 = __float2bfloat16(v);
    s0f = __bfloat162float(h0);
    s1f = v - s0f;
}
__device__ __forceinline__ float sigf(float x)  { return __fdividef(1.f, 1.f + __expf(-x)); }
__device__ __forceinline__ float tanha(float x) { return __fdividef(2.f, 1.f + __expf(-2.f * x)) - 1.f; }

// ---------------------------------------------------------------------------
// Kernel 0: pack weights into mma-fragment records + fold bias
// record e = n*64 + kb*4 + t : 16B = {pack(s0@2t,s0@2t+1), pack(s0@2t+8,s0@2t+9),
//                                    pack(s1@2t,s1@2t+1), pack(s1@2t+8,s1@2t+9)}
// ---------------------------------------------------------------------------
__global__ void prep_kernel(const float* __restrict__ w_ih, const float* __restrict__ w_hh,
                            const float* __restrict__ b_ih, const float* __restrict__ b_hh) {
    int idx = blockIdx.x * blockDim.x + threadIdx.x;   // 65536
    if (idx >= NG * 64) return;
    int n = idx >> 6, kb = (idx >> 2) & 15, t = idx & 3;
    int k0 = kb * 16 + 2 * t;
#pragma unroll
    for (int w = 0; w < 2; w++) {
        const float* src = w ? w_hh : w_ih;
        float v00 = src[n * NH + k0],     v01 = src[n * NH + k0 + 1];
        float v10 = src[n * NH + k0 + 8], v11 = src[n * NH + k0 + 9];
        float a, b, c, d, e, f, g2, h2;
        split2(v00, a, b); split2(v01, c, d); split2(v10, e, f); split2(v11, g2, h2);
        uint4 q;
        q.x = pk2bf(a, c);  q.y = pk2bf(e, g2);
        q.z = pk2bf(b, d);  q.w = pk2bf(f, h2);
        (w ? g_qhh : g_qih)[idx] = q;
    }
    if (idx < NG) g_bias2[idx] = b_ih[idx] + b_hh[idx];
}

// ---------------------------------------------------------------------------
// Kernel 1: x0 = relu(x @ w_in^T + b_in)  (fp32)
// ---------------------------------------------------------------------------
__global__ void __launch_bounds__(256) input_kernel(const float* __restrict__ x,
                                                    const float* __restrict__ w_in,
                                                    const float* __restrict__ b_in) {
    __shared__ float w_s[NH][NX + 1];
    __shared__ float xt[16][NX];
    int tid = threadIdx.x;
    size_t r0 = (size_t)blockIdx.x * 16;
#pragma unroll
    for (int i = 0; i < NX; i++) w_s[tid][i] = w_in[tid * NX + i];
    xt[tid >> 4][tid & 15] = x[r0 * NX + tid];
    __syncthreads();
    float b = b_in[tid];
    for (int r = 0; r < 16; r++) {
        float acc = b;
#pragma unroll
        for (int i = 0; i < NX; i++) acc += xt[r][i] * w_s[tid][i];
        g_x0[(r0 + r) * NH + tid] = fmaxf(acc, 0.f);
    }
}

// ---------------------------------------------------------------------------
// Kernel 2: xg(chunk) = x0(chunk) @ w_ih^T + bias2   (mma.sync, 3-term split)
// CTA: 128 rows, loops 8 n-tiles of 128. 8 warps = 2(m) x 4(n).
// A smem split on the fly from fp32 x0 ([split][128][264 bf16], 528B rows).
// ---------------------------------------------------------------------------
#define G_SMEM (2 * 128 * 528)

__global__ void __launch_bounds__(256, 1) xg_gemm_kernel(int t0) {
    extern __shared__ char sm[];
    char* A0 = sm;
    char* A1 = sm + 128 * 528;
    int tid = threadIdx.x, lane = tid & 31, w = tid >> 5;
    int wm = w >> 2, wn = w & 3;
    int g = lane >> 2, t = lane & 3;
    size_t m0l = (size_t)blockIdx.x * 128;                 // row within chunk
    size_t m0g = (size_t)t0 * NGRID + m0l;                 // row in g_x0

    // stage + split A
    for (int c = tid; c < 4096; c += 256) {
        int r = c >> 5, k8 = (c & 31) << 3;
        const float* src = g_x0 + (m0g + r) * NH + k8;
        float4 v0 = *(const float4*)src;
        float4 v1 = *(const float4*)(src + 4);
        float vv[8] = { v0.x, v0.y, v0.z, v0.w, v1.x, v1.y, v1.z, v1.w };
        uint32_t hw[4], lw[4];
#pragma unroll
        for (int i = 0; i < 4; i++) {
            float s0a, s1a, s0b, s1b;
            split2(vv[2 * i], s0a, s1a); split2(vv[2 * i + 1], s0b, s1b);
            hw[i] = pk2bf(s0a, s0b); lw[i] = pk2bf(s1a, s1b);
        }
        *(uint4*)(A0 + r * 528 + k8 * 2) = make_uint4(hw[0], hw[1], hw[2], hw[3]);
        *(uint4*)(A1 + r * 528 + k8 * 2) = make_uint4(lw[0], lw[1], lw[2], lw[3]);
    }
    __syncthreads();

    uint32_t lbase = (uint32_t)((wm * 64 + (lane & 15)) * 528 + ((lane >> 4) << 3) * 2);
    uint32_t a0b = su32(A0) + lbase;
    uint32_t a1b = su32(A1) + lbase;

    for (int nt = 0; nt < 8; nt++) {
        float acc[4][4][4];
#pragma unroll
        for (int mt = 0; mt < 4; mt++)
#pragma unroll
            for (int nb = 0; nb < 4; nb++)
#pragma unroll
                for (int r = 0; r < 4; r++) acc[mt][nb][r] = 0.f;

        unsigned bofs[4];
#pragma unroll
        for (int nb = 0; nb < 4; nb++)
            bofs[nb] = (unsigned)((nt * 128 + wn * 32 + nb * 8 + g) * 64 + t);

        uint4 Bc[4], Bn[4];
#pragma unroll
        for (int nb = 0; nb < 4; nb++) Bc[nb] = g_qih[bofs[nb]];

#pragma unroll
        for (int kb = 0; kb < 16; kb++) {
            uint32_t af0[4][4], af1[4][4];
#pragma unroll
            for (int mt = 0; mt < 4; mt++) {
                ldmat4(af0[mt], a0b + mt * 16 * 528 + kb * 32);
                ldmat4(af1[mt], a1b + mt * 16 * 528 + kb * 32);
            }
            if (kb < 15) {
#pragma unroll
                for (int nb = 0; nb < 4; nb++) Bn[nb] = g_qih[bofs[nb] + (kb + 1) * 4];
            }
#pragma unroll
            for (int mt = 0; mt < 4; mt++)
#pragma unroll
                for (int nb = 0; nb < 4; nb++) {
                    mma_bf16(acc[mt][nb][0], acc[mt][nb][1], acc[mt][nb][2], acc[mt][nb][3],
                             af0[mt][0], af0[mt][1], af0[mt][2], af0[mt][3], Bc[nb].x, Bc[nb].y);
                    mma_bf16(acc[mt][nb][0], acc[mt][nb][1], acc[mt][nb][2], acc[mt][nb][3],
                             af0[mt][0], af0[mt][1], af0[mt][2], af0[mt][3], Bc[nb].z, Bc[nb].w);
                    mma_bf16(acc[mt][nb][0], acc[mt][nb][1], acc[mt][nb][2], acc[mt][nb][3],
                             af1[mt][0], af1[mt][1], af1[mt][2], af1[mt][3], Bc[nb].x, Bc[nb].y);
                }
            if (kb < 15) {
#pragma unroll
                for (int nb = 0; nb < 4; nb++) Bc[nb] = Bn[nb];
            }
        }

#pragma unroll
        for (int nb = 0; nb < 4; nb++) {
            int col = nt * 128 + wn * 32 + nb * 8 + 2 * t;
            float2 bs = *(const float2*)(g_bias2 + col);
#pragma unroll
            for (int mt = 0; mt < 4; mt++) {
                size_t row = m0l + wm * 64 + mt * 16 + g;
                float2 v0 = { acc[mt][nb][0] + bs.x, acc[mt][nb][1] + bs.y };
                float2 v1 = { acc[mt][nb][2] + bs.x, acc[mt][nb][3] + bs.y };
                *(float2*)(g_xg + row * NG + col)       = v0;
                *(float2*)(g_xg + (row + 8) * NG + col) = v1;
            }
        }
    }
}

// ---------------------------------------------------------------------------
// Kernel 3: recurrent scan chunk on mma.sync.
// 128 CTAs x 256 thr; m16 = 16 cells; warp w owns hidden [32w,32w+32) over
// all 4 gate groups -> pointwise register-resident. State spilled per chunk.
// ---------------------------------------------------------------------------
#define XPAD 1028
#define XGB  (16 * XPAD * 4)          /* 65792 B */
#define S_XG 0
#define S_HS (2 * XGB)
#define S_RED (S_HS + 4 * HSB)
#define S_SMEM (S_RED + 512)

__global__ void __launch_bounds__(256, 1) lstm_scan(int t0,
                                                    const float* __restrict__ w_out,
                                                    const float* __restrict__ b_out,
                                                    float* __restrict__ out) {
    extern __shared__ char sm[];
    float* red = (float*)(sm + S_RED);
    int tid = threadIdx.x, lane = tid & 31, w = tid >> 5;
    int g = lane >> 2, t = lane & 3;
    int b0 = blockIdx.x * CELLS;

    float cst[16];
    if (t0 == 0) {
        for (int i = tid; i < (2 * HSB) / 4; i += 256) ((uint32_t*)(sm + S_HS))[i] = 0;
#pragma unroll
        for (int i = 0; i < 16; i++) cst[i] = 0.f;
    } else {
        const uint32_t* hp = g_hs + (size_t)blockIdx.x * (2 * HSB / 4);
        for (int i = tid; i < (2 * HSB) / 4; i += 256) ((uint32_t*)(sm + S_HS))[i] = hp[i];
        const float* cp = g_cs + ((size_t)blockIdx.x * 256 + tid) * 16;
#pragma unroll
        for (int i = 0; i < 16; i++) cst[i] = cp[i];
    }

    // prefetch xg for local step 0 into buffer 0
    {
        const char* src = (const char*)(g_xg + ((size_t)0 * NGRID + b0) * NG);
        uint32_t dst = su32(sm) + S_XG;
#pragma unroll
        for (int r = 0; r < 16; r++)
            cpa16(dst + r * (XPAD * 4) + tid * 16, src + r * 4096 + tid * 16);
        CPA_COMMIT();
    }

    float2 wo[4];
#pragma unroll
    for (int nb = 0; nb < 4; nb++) wo[nb] = *(const float2*)(w_out + w * 32 + nb * 8 + 2 * t);
    float bout = b_out[0];

    unsigned bofs[4][4];
#pragma unroll
    for (int G = 0; G < 4; G++)
#pragma unroll
        for (int nb = 0; nb < 4; nb++)
            bofs[G][nb] = (unsigned)((G * 256 + w * 32 + nb * 8 + g) * 64 + t);

    uint32_t hlbase = (uint32_t)((lane & 15) * 528 + ((lane >> 4) << 3) * 2);

    for (int st = 0; st < TC; st++) {
        CPA_WAIT0();
        __syncthreads();
        int rb = st & 1, wb = rb ^ 1;

        float* xb = (float*)(sm + S_XG) + rb * (XGB / 4);
        float acc[4][4][4];
#pragma unroll
        for (int G = 0; G < 4; G++)
#pragma unroll
            for (int nb = 0; nb < 4; nb++) {
                int col = G * 256 + w * 32 + nb * 8 + 2 * t;
                float2 v01 = *(float2*)(xb + g * XPAD + col);
                float2 v23 = *(float2*)(xb + (g + 8) * XPAD + col);
                acc[G][nb][0] = v01.x; acc[G][nb][1] = v01.y;
                acc[G][nb][2] = v23.x; acc[G][nb][3] = v23.y;
            }

        if (st + 1 < TC) {
            const char* src = (const char*)(g_xg + ((size_t)(st + 1) * NGRID + b0) * NG);
            uint32_t dst = su32(sm) + S_XG + wb * XGB;
#pragma unroll
            for (int r = 0; r < 16; r++)
                cpa16(dst + r * (XPAD * 4) + tid * 16, src + r * 4096 + tid * 16);
        }
        CPA_COMMIT();

        uint32_t h0b = su32(sm) + S_HS + rb * (2 * HSB) + hlbase;
        uint32_t h1b = h0b + HSB;
#pragma unroll
        for (int kb = 0; kb < 16; kb++) {
            uint32_t a0[4], a1[4];
            ldmat4(a0, h0b + kb * 32);
            ldmat4(a1, h1b + kb * 32);
            uint4 B[2][4];
#pragma unroll
            for (int G = 0; G < 2; G++)
#pragma unroll
                for (int nb = 0; nb < 4; nb++) B[G][nb] = g_qhh[bofs[G][nb] + kb * 4];
#pragma unroll
            for (int G = 0; G < 2; G++)
#pragma unroll
                for (int nb = 0; nb < 4; nb++) {
                    mma_bf16(acc[G][nb][0], acc[G][nb][1], acc[G][nb][2], acc[G][nb][3],
                             a0[0], a0[1], a0[2], a0[3], B[G][nb].x, B[G][nb].y);
                    mma_bf16(acc[G][nb][0], acc[G][nb][1], acc[G][nb][2], acc[G][nb][3],
                             a0[0], a0[1], a0[2], a0[3], B[G][nb].z, B[G][nb].w);
                    mma_bf16(acc[G][nb][0], acc[G][nb][1], acc[G][nb][2], acc[G][nb][3],
                             a1[0], a1[1], a1[2], a1[3], B[G][nb].x, B[G][nb].y);
                }
#pragma unroll
            for (int G = 2; G < 4; G++)
#pragma unroll
                for (int nb = 0; nb < 4; nb++) B[G - 2][nb] = g_qhh[bofs[G][nb] + kb * 4];
#pragma unroll
            for (int G = 2; G < 4; G++)
#pragma unroll
                for (int nb = 0; nb < 4; nb++) {
                    mma_bf16(acc[G][nb][0], acc[G][nb][1], acc[G][nb][2], acc[G][nb][3],
                             a0[0], a0[1], a0[2], a0[3], B[G - 2][nb].x, B[G - 2][nb].y);
                    mma_bf16(acc[G][nb][0], acc[G][nb][1], acc[G][nb][2], acc[G][nb][3],
                             a0[0], a0[1], a0[2], a0[3], B[G - 2][nb].z, B[G - 2][nb].w);
                    mma_bf16(acc[G][nb][0], acc[G][nb][1], acc[G][nb][2], acc[G][nb][3],
                             a1[0], a1[1], a1[2], a1[3], B[G - 2][nb].x, B[G - 2][nb].y);
                }
        }

        // pointwise cell + h restage + fused output partials
        char* hw0 = sm + S_HS + wb * (2 * HSB);
        char* hw1 = hw0 + HSB;
        float p0 = 0.f, p1 = 0.f;
#pragma unroll
        for (int nb = 0; nb < 4; nb++) {
            int j0 = w * 32 + nb * 8 + 2 * t;
            {
                float i0 = sigf(acc[0][nb][0]), f0 = sigf(acc[1][nb][0]);
                float g0 = tanha(acc[2][nb][0]), o0 = sigf(acc[3][nb][0]);
                float i1 = sigf(acc[0][nb][1]), f1 = sigf(acc[1][nb][1]);
                float g1 = tanha(acc[2][nb][1]), o1 = sigf(acc[3][nb][1]);
                float& cA = cst[nb * 4 + 0]; cA = f0 * cA + i0 * g0;
                float& cB = cst[nb * 4 + 1]; cB = f1 * cB + i1 * g1;
                float hA = o0 * tanha(cA), hB = o1 * tanha(cB);
                p0 += hA * wo[nb].x + hB * wo[nb].y;
                float sA, rA, sB, rB; split2(hA, sA, rA); split2(hB, sB, rB);
                *(uint32_t*)(hw0 + g * 528 + j0 * 2) = pk2bf(sA, sB);
                *(uint32_t*)(hw1 + g * 528 + j0 * 2) = pk2bf(rA, rB);
            }
            {
                float i0 = sigf(acc[0][nb][2]), f0 = sigf(acc[1][nb][2]);
                float g0 = tanha(acc[2][nb][2]), o0 = sigf(acc[3][nb][2]);
                float i1 = sigf(acc[0][nb][3]), f1 = sigf(acc[1][nb][3]);
                float g1 = tanha(acc[2][nb][3]), o1 = sigf(acc[3][nb][3]);
                float& cA = cst[nb * 4 + 2]; cA = f0 * cA + i0 * g0;
                float& cB = cst[nb * 4 + 3]; cB = f1 * cB + i1 * g1;
                float hA = o0 * tanha(cA), hB = o1 * tanha(cB);
                p1 += hA * wo[nb].x + hB * wo[nb].y;
                float sA, rA, sB, rB; split2(hA, sA, rA); split2(hB, sB, rB);
                *(uint32_t*)(hw0 + (g + 8) * 528 + j0 * 2) = pk2bf(sA, sB);
                *(uint32_t*)(hw1 + (g + 8) * 528 + j0 * 2) = pk2bf(rA, rB);
            }
        }
        p0 += __shfl_xor_sync(0xffffffffu, p0, 1);
        p0 += __shfl_xor_sync(0xffffffffu, p0, 2);
        p1 += __shfl_xor_sync(0xffffffffu, p1, 1);
        p1 += __shfl_xor_sync(0xffffffffu, p1, 2);
        if (t == 0) { red[g * 8 + w] = p0; red[(g + 8) * 8 + w] = p1; }
        __syncthreads();
        if (tid < 16) {
            float s = bout;
#pragma unroll
            for (int k = 0; k < 8; k++) s += red[tid * 8 + k];
            out[(size_t)(t0 + st) * NGRID + b0 + tid] = s;
        }
    }

    // spill state: final h is in buffer 1 (TC odd: last wb = 1)
    uint32_t* hp = g_hs + (size_t)blockIdx.x * (2 * HSB / 4);
    const uint32_t* hsrc = (const uint32_t*)(sm + S_HS + 2 * HSB);
    for (int i = tid; i < (2 * HSB) / 4; i += 256) hp[i] = hsrc[i];
    float* cp = g_cs + ((size_t)blockIdx.x * 256 + tid) * 16;
#pragma unroll
    for (int i = 0; i < 16; i++) cp[i] = cst[i];
}

// ---------------------------------------------------------------------------
extern "C" void kernel_launch(void* const* d_in, const int* in_sizes, int n_in,
                              void* d_out, int out_size) {
    const float* x     = (const float*)d_in[0];
    const float* w_in  = (const float*)d_in[1];
    const float* b_in  = (const float*)d_in[2];
    const float* w_ih  = (const float*)d_in[3];
    const float* w_hh  = (const float*)d_in[4];
    const float* b_ih  = (const float*)d_in[5];
    const float* b_hh  = (const float*)d_in[6];
    const float* w_out = (const float*)d_in[7];
    const float* b_out = (const float*)d_in[8];
    float* out = (float*)d_out;

    cudaFuncSetAttribute(xg_gemm_kernel, cudaFuncAttributeMaxDynamicSharedMemorySize, G_SMEM);
    cudaFuncSetAttribute(lstm_scan,      cudaFuncAttributeMaxDynamicSharedMemorySize, S_SMEM);

    prep_kernel<<<(NG * 64 + 255) / 256, 256>>>(w_ih, w_hh, b_ih, b_hh);
    input_kernel<<<(NTT * NGRID) / 16, 256>>>(x, w_in, b_in);
    for (int c = 0; c < NCH; c++) {
        int t0 = c * TC;
        xg_gemm_kernel<<<CROWS / 128, 256, G_SMEM>>>(t0);
        lstm_scan<<<NBLK, 256, S_SMEM>>>(t0, w_out, b_out, out);
    }
}

// round 6
// speedup vs baseline: 3.1470x; 1.0605x over previous
#include <cuda_runtime.h>
#include <cuda_fp16.h>
#include <cuda_bf16.h>
#include <cstdint>

#define NTT   365
#define NGRID 2048
#define NX    16
#define NH    256
#define NG    1024
#define CELLS 16
#define NBLK  (NGRID/CELLS)    /* 128 */
#define ROWS  (NTT*NGRID)      /* 747520 */

// ---------------------------------------------------------------------------
// Device-global scratch (~1.54 GB total; must stay < 2 GB for host link)
// ---------------------------------------------------------------------------
__device__ __half g_xg[(size_t)ROWS * NG];   // 1.53 GB fp16 xg for ALL steps
__device__ uint4 g_qih[NG * 64];             // packed w_ih frag records (1MB)
__device__ uint4 g_qhh[NG * 64];             // packed w_hh frag records (1MB)
__device__ float g_bias2[NG];

// ---------------------------------------------------------------------------
// PTX helpers (sm_100 baseline-safe: mma.sync / ldmatrix / cp.async only)
// ---------------------------------------------------------------------------
__device__ __forceinline__ uint32_t su32(const void* p) {
    uint32_t a;
    asm("{ .reg .u64 t; cvta.to.shared.u64 t, %1; cvt.u32.u64 %0, t; }" : "=r"(a) : "l"(p));
    return a;
}
__device__ __forceinline__ void mma_bf16(float& c0, float& c1, float& c2, float& c3,
                                         uint32_t a0, uint32_t a1, uint32_t a2, uint32_t a3,
                                         uint32_t b0, uint32_t b1) {
    asm volatile(
        "mma.sync.aligned.m16n8k16.row.col.f32.bf16.bf16.f32 "
        "{%0,%1,%2,%3},{%4,%5,%6,%7},{%8,%9},{%0,%1,%2,%3};"
        : "+f"(c0), "+f"(c1), "+f"(c2), "+f"(c3)
        : "r"(a0), "r"(a1), "r"(a2), "r"(a3), "r"(b0), "r"(b1));
}
__device__ __forceinline__ void ldmat4(uint32_t* r, uint32_t addr) {
    asm volatile("ldmatrix.sync.aligned.m8n8.x4.shared.b16 {%0,%1,%2,%3},[%4];"
                 : "=r"(r[0]), "=r"(r[1]), "=r"(r[2]), "=r"(r[3]) : "r"(addr));
}
__device__ __forceinline__ void cpa16(uint32_t s, const void* g) {
    asm volatile("cp.async.cg.shared.global [%0],[%1],16;" :: "r"(s), "l"(g));
}
#define CPA_COMMIT() asm volatile("cp.async.commit_group;" ::: "memory")
#define CPA_WAIT0()  asm volatile("cp.async.wait_group 0;" ::: "memory")

__device__ __forceinline__ uint32_t pk2bf(float lo, float hi) {
    uint32_t l = (uint32_t)__bfloat16_as_ushort(__float2bfloat16(lo));
    uint32_t h = (uint32_t)__bfloat16_as_ushort(__float2bfloat16(hi));
    return l | (h << 16);
}
__device__ __forceinline__ void split2(float v, float& s0f, float& s1f) {
    __nv_bfloat16 h0 = __float2bfloat16(v);
    s0f = __bfloat162float(h0);
    s1f = v - s0f;
}
__device__ __forceinline__ float sigf(float x)  { return __fdividef(1.f, 1.f + __expf(-x)); }
__device__ __forceinline__ float tanha(float x) { return __fdividef(2.f, 1.f + __expf(-2.f * x)) - 1.f; }

// ---------------------------------------------------------------------------
// Kernel 0: pack weights into mma-fragment records + fold bias
// ---------------------------------------------------------------------------
__global__ void prep_kernel(const float* __restrict__ w_ih, const float* __restrict__ w_hh,
                            const float* __restrict__ b_ih, const float* __restrict__ b_hh) {
    int idx = blockIdx.x * blockDim.x + threadIdx.x;   // 65536
    if (idx >= NG * 64) return;
    int n = idx >> 6, kb = (idx >> 2) & 15, t = idx & 3;
    int k0 = kb * 16 + 2 * t;
#pragma unroll
    for (int w = 0; w < 2; w++) {
        const float* src = w ? w_hh : w_ih;
        float v00 = src[n * NH + k0],     v01 = src[n * NH + k0 + 1];
        float v10 = src[n * NH + k0 + 8], v11 = src[n * NH + k0 + 9];
        float a, b, c, d, e, f, g2, h2;
        split2(v00, a, b); split2(v01, c, d); split2(v10, e, f); split2(v11, g2, h2);
        uint4 q;
        q.x = pk2bf(a, c);  q.y = pk2bf(e, g2);
        q.z = pk2bf(b, d);  q.w = pk2bf(f, h2);
        (w ? g_qhh : g_qih)[idx] = q;
    }
    if (idx < NG) g_bias2[idx] = b_ih[idx] + b_hh[idx];
}

// ---------------------------------------------------------------------------
// Kernel 1: fused input+xg GEMM.
// Per CTA (512 thr, 16 warps = 4m x 4n, warp tile 32x32):
//   x0 = relu(x @ w_in^T + b_in) computed on-chip (K=16, FMA) -> bf16 split in smem
//   xg = x0 @ w_ih^T + bias2 (3-term bf16 mma.sync) -> fp16 to gmem
// ---------------------------------------------------------------------------
#define A_TILE (128 * 528)                         /* 67584 */
#define G_SMEM (2 * A_TILE + 8192 + 256 * 17 * 4)  /* 160768 */

__global__ void __launch_bounds__(512, 1) xg_gemm_kernel(const float* __restrict__ x,
                                                         const float* __restrict__ w_in,
                                                         const float* __restrict__ b_in) {
    extern __shared__ char sm[];
    char*  A0 = sm;
    char*  A1 = sm + A_TILE;
    float* xs = (float*)(sm + 2 * A_TILE);             // [128][16]
    float* ws = (float*)(sm + 2 * A_TILE + 8192);      // [256][17], last = bias
    int tid = threadIdx.x, lane = tid & 31, w = tid >> 5;
    int wm = w >> 2, wn = w & 3;
    int g = lane >> 2, t = lane & 3;
    size_t m0 = (size_t)blockIdx.x * 128;

    // stage x rows + w_in (+bias into pad slot)
    ((uint4*)xs)[tid] = ((const uint4*)(x + m0 * NX))[tid];
    {
        int h = tid >> 1, i0 = (tid & 1) * 8;
        const float* src = w_in + h * NX + i0;
#pragma unroll
        for (int i = 0; i < 8; i++) ws[h * 17 + i0 + i] = src[i];
        if ((tid & 1) == 0) ws[h * 17 + 16] = b_in[h];
    }
    __syncthreads();

    // x0 = relu(x @ w_in^T + b), bf16 split into A0/A1
    for (int it = 0; it < 64; it++) {
        int idx = it * 512 + tid, r = idx >> 8, h = idx & 255;
        float acc = ws[h * 17 + 16];
#pragma unroll
        for (int i = 0; i < 16; i++) acc += xs[r * 16 + i] * ws[h * 17 + i];
        float v = fmaxf(acc, 0.f), s0, s1; split2(v, s0, s1);
        *(__nv_bfloat16*)(A0 + r * 528 + h * 2) = __float2bfloat16(s0);
        *(__nv_bfloat16*)(A1 + r * 528 + h * 2) = __float2bfloat16(s1);
    }
    __syncthreads();

    uint32_t lbase = (uint32_t)((wm * 32 + (lane & 15)) * 528 + (lane >> 4) * 16);
    uint32_t a0b = su32(A0) + lbase;
    uint32_t a1b = su32(A1) + lbase;

    for (int nt = 0; nt < 8; nt++) {
        float acc[2][4][4];
#pragma unroll
        for (int mt = 0; mt < 2; mt++)
#pragma unroll
            for (int nb = 0; nb < 4; nb++)
#pragma unroll
                for (int r = 0; r < 4; r++) acc[mt][nb][r] = 0.f;

        unsigned bofs[4];
#pragma unroll
        for (int nb = 0; nb < 4; nb++)
            bofs[nb] = (unsigned)((nt * 128 + wn * 32 + nb * 8 + g) * 64 + t);

        uint4 Bc[4], Bn[4];
#pragma unroll
        for (int nb = 0; nb < 4; nb++) Bc[nb] = g_qih[bofs[nb]];

#pragma unroll
        for (int kb = 0; kb < 16; kb++) {
            uint32_t af0[2][4], af1[2][4];
#pragma unroll
            for (int mt = 0; mt < 2; mt++) {
                ldmat4(af0[mt], a0b + mt * 16 * 528 + kb * 32);
                ldmat4(af1[mt], a1b + mt * 16 * 528 + kb * 32);
            }
            if (kb < 15) {
#pragma unroll
                for (int nb = 0; nb < 4; nb++) Bn[nb] = g_qih[bofs[nb] + (kb + 1) * 4];
            }
#pragma unroll
            for (int mt = 0; mt < 2; mt++)
#pragma unroll
                for (int nb = 0; nb < 4; nb++) {
                    mma_bf16(acc[mt][nb][0], acc[mt][nb][1], acc[mt][nb][2], acc[mt][nb][3],
                             af0[mt][0], af0[mt][1], af0[mt][2], af0[mt][3], Bc[nb].x, Bc[nb].y);
                    mma_bf16(acc[mt][nb][0], acc[mt][nb][1], acc[mt][nb][2], acc[mt][nb][3],
                             af0[mt][0], af0[mt][1], af0[mt][2], af0[mt][3], Bc[nb].z, Bc[nb].w);
                    mma_bf16(acc[mt][nb][0], acc[mt][nb][1], acc[mt][nb][2], acc[mt][nb][3],
                             af1[mt][0], af1[mt][1], af1[mt][2], af1[mt][3], Bc[nb].x, Bc[nb].y);
                }
            if (kb < 15) {
#pragma unroll
                for (int nb = 0; nb < 4; nb++) Bc[nb] = Bn[nb];
            }
        }

#pragma unroll
        for (int nb = 0; nb < 4; nb++) {
            int col = nt * 128 + wn * 32 + nb * 8 + 2 * t;
            float2 bs = *(const float2*)(g_bias2 + col);
#pragma unroll
            for (int mt = 0; mt < 2; mt++) {
                size_t row = m0 + wm * 32 + mt * 16 + g;
                *(__half2*)(g_xg + row * NG + col) =
                    __floats2half2_rn(acc[mt][nb][0] + bs.x, acc[mt][nb][1] + bs.y);
                *(__half2*)(g_xg + (row + 8) * NG + col) =
                    __floats2half2_rn(acc[mt][nb][2] + bs.x, acc[mt][nb][3] + bs.y);
            }
        }
    }
}

// ---------------------------------------------------------------------------
// Kernel 2: full 365-step recurrent scan on mma.sync.
// 128 CTAs x 512 thr (16 warps); warp w owns hidden [16w,16w+16) over all
// 4 gate groups -> pointwise register-resident. No chunking, no state spill.
// ---------------------------------------------------------------------------
#define XROW 2064                       /* fp16 xg row stride (bytes), conflict-free */
#define XGB  (16 * XROW)                /* 33024 */
#define S_HS (2 * XGB)                  /* 66048 */
#define HSB  (16 * 528)                 /* 8448 */
#define S_RED (S_HS + 4 * HSB)          /* 99840 */
#define S_SMEM (S_RED + 1024)           /* 100864 */

__global__ void __launch_bounds__(512, 1) lstm_scan(const float* __restrict__ w_out,
                                                    const float* __restrict__ b_out,
                                                    float* __restrict__ out) {
    extern __shared__ char sm[];
    float* red = (float*)(sm + S_RED);
    int tid = threadIdx.x, lane = tid & 31, w = tid >> 5;
    int g = lane >> 2, t = lane & 3;
    int b0 = blockIdx.x * CELLS;

    // zero h tiles (buffer 0, both splits); c-state in regs
    for (int i = tid; i < (2 * HSB) / 4; i += 512) ((uint32_t*)(sm + S_HS))[i] = 0;
    float cst[8];
#pragma unroll
    for (int i = 0; i < 8; i++) cst[i] = 0.f;

    // prefetch xg step 0 (16 cells x 1024 fp16, contiguous 32KB)
    {
        const char* src = (const char*)(g_xg + (size_t)b0 * NG);
        uint32_t dst = su32(sm);
        for (int c = tid; c < 2048; c += 512)
            cpa16(dst + (c >> 7) * XROW + (c & 127) * 16, src + c * 16);
        CPA_COMMIT();
    }

    float2 wo[2];
#pragma unroll
    for (int nb = 0; nb < 2; nb++) wo[nb] = *(const float2*)(w_out + w * 16 + nb * 8 + 2 * t);
    float bout = b_out[0];

    unsigned bofs[4][2];
#pragma unroll
    for (int G = 0; G < 4; G++)
#pragma unroll
        for (int nb = 0; nb < 2; nb++)
            bofs[G][nb] = (unsigned)((G * 256 + w * 16 + nb * 8 + g) * 64 + t);

    uint32_t hlbase = (uint32_t)((lane & 15) * 528 + (lane >> 4) * 16);

    for (int st = 0; st < NTT; st++) {
        CPA_WAIT0();
        __syncthreads();
        int rb = st & 1, wb = rb ^ 1;

        // accumulator init = xg (fp16 -> f32)
        char* xb = sm + rb * XGB;
        float acc[4][2][4];
#pragma unroll
        for (int G = 0; G < 4; G++)
#pragma unroll
            for (int nb = 0; nb < 2; nb++) {
                int col = G * 256 + w * 16 + nb * 8 + 2 * t;
                float2 f01 = __half22float2(*(__half2*)(xb + g * XROW + col * 2));
                float2 f23 = __half22float2(*(__half2*)(xb + (g + 8) * XROW + col * 2));
                acc[G][nb][0] = f01.x; acc[G][nb][1] = f01.y;
                acc[G][nb][2] = f23.x; acc[G][nb][3] = f23.y;
            }

        // prefetch next step's xg
        if (st + 1 < NTT) {
            const char* src = (const char*)(g_xg + ((size_t)(st + 1) * NGRID + b0) * NG);
            uint32_t dst = su32(sm) + wb * XGB;
            for (int c = tid; c < 2048; c += 512)
                cpa16(dst + (c >> 7) * XROW + (c & 127) * 16, src + c * 16);
        }
        CPA_COMMIT();

        // h(prev) @ w_hh^T over K=256 (3-term bf16 split)
        uint32_t h0b = su32(sm) + S_HS + rb * (2 * HSB) + hlbase;
        uint32_t h1b = h0b + HSB;
#pragma unroll
        for (int kb = 0; kb < 16; kb++) {
            uint32_t a0[4], a1[4];
            ldmat4(a0, h0b + kb * 32);
            ldmat4(a1, h1b + kb * 32);
            uint4 B[4][2];
#pragma unroll
            for (int G = 0; G < 4; G++)
#pragma unroll
                for (int nb = 0; nb < 2; nb++) B[G][nb] = g_qhh[bofs[G][nb] + kb * 4];
#pragma unroll
            for (int G = 0; G < 4; G++)
#pragma unroll
                for (int nb = 0; nb < 2; nb++) {
                    mma_bf16(acc[G][nb][0], acc[G][nb][1], acc[G][nb][2], acc[G][nb][3],
                             a0[0], a0[1], a0[2], a0[3], B[G][nb].x, B[G][nb].y);
                    mma_bf16(acc[G][nb][0], acc[G][nb][1], acc[G][nb][2], acc[G][nb][3],
                             a0[0], a0[1], a0[2], a0[3], B[G][nb].z, B[G][nb].w);
                    mma_bf16(acc[G][nb][0], acc[G][nb][1], acc[G][nb][2], acc[G][nb][3],
                             a1[0], a1[1], a1[2], a1[3], B[G][nb].x, B[G][nb].y);
                }
        }

        // pointwise cell + h restage + fused output partials
        char* hw0 = sm + S_HS + wb * (2 * HSB);
        char* hw1 = hw0 + HSB;
        float p0 = 0.f, p1 = 0.f;
#pragma unroll
        for (int nb = 0; nb < 2; nb++) {
            int j0 = w * 16 + nb * 8 + 2 * t;
            {   // cell g (regs 0,1)
                float i0 = sigf(acc[0][nb][0]), f0 = sigf(acc[1][nb][0]);
                float g0 = tanha(acc[2][nb][0]), o0 = sigf(acc[3][nb][0]);
                float i1 = sigf(acc[0][nb][1]), f1 = sigf(acc[1][nb][1]);
                float g1 = tanha(acc[2][nb][1]), o1 = sigf(acc[3][nb][1]);
                float& cA = cst[nb * 4 + 0]; cA = f0 * cA + i0 * g0;
                float& cB = cst[nb * 4 + 1]; cB = f1 * cB + i1 * g1;
                float hA = o0 * tanha(cA), hB = o1 * tanha(cB);
                p0 += hA * wo[nb].x + hB * wo[nb].y;
                float sA, rA, sB, rB; split2(hA, sA, rA); split2(hB, sB, rB);
                *(uint32_t*)(hw0 + g * 528 + j0 * 2) = pk2bf(sA, sB);
                *(uint32_t*)(hw1 + g * 528 + j0 * 2) = pk2bf(rA, rB);
            }
            {   // cell g+8 (regs 2,3)
                float i0 = sigf(acc[0][nb][2]), f0 = sigf(acc[1][nb][2]);
                float g0 = tanha(acc[2][nb][2]), o0 = sigf(acc[3][nb][2]);
                float i1 = sigf(acc[0][nb][3]), f1 = sigf(acc[1][nb][3]);
                float g1 = tanha(acc[2][nb][3]), o1 = sigf(acc[3][nb][3]);
                float& cA = cst[nb * 4 + 2]; cA = f0 * cA + i0 * g0;
                float& cB = cst[nb * 4 + 3]; cB = f1 * cB + i1 * g1;
                float hA = o0 * tanha(cA), hB = o1 * tanha(cB);
                p1 += hA * wo[nb].x + hB * wo[nb].y;
                float sA, rA, sB, rB; split2(hA, sA, rA); split2(hB, sB, rB);
                *(uint32_t*)(hw0 + (g + 8) * 528 + j0 * 2) = pk2bf(sA, sB);
                *(uint32_t*)(hw1 + (g + 8) * 528 + j0 * 2) = pk2bf(rA, rB);
            }
        }
        p0 += __shfl_xor_sync(0xffffffffu, p0, 1);
        p0 += __shfl_xor_sync(0xffffffffu, p0, 2);
        p1 += __shfl_xor_sync(0xffffffffu, p1, 1);
        p1 += __shfl_xor_sync(0xffffffffu, p1, 2);
        if (t == 0) { red[g * 16 + w] = p0; red[(g + 8) * 16 + w] = p1; }
        __syncthreads();
        if (tid < 16) {
            float s = bout;
#pragma unroll
            for (int k = 0; k < 16; k++) s += red[tid * 16 + k];
            out[(size_t)st * NGRID + b0 + tid] = s;
        }
    }
}

// ---------------------------------------------------------------------------
extern "C" void kernel_launch(void* const* d_in, const int* in_sizes, int n_in,
                              void* d_out, int out_size) {
    const float* x     = (const float*)d_in[0];
    const float* w_in  = (const float*)d_in[1];
    const float* b_in  = (const float*)d_in[2];
    const float* w_ih  = (const float*)d_in[3];
    const float* w_hh  = (const float*)d_in[4];
    const float* b_ih  = (const float*)d_in[5];
    const float* b_hh  = (const float*)d_in[6];
    const float* w_out = (const float*)d_in[7];
    const float* b_out = (const float*)d_in[8];
    float* out = (float*)d_out;

    cudaFuncSetAttribute(xg_gemm_kernel, cudaFuncAttributeMaxDynamicSharedMemorySize, G_SMEM);
    cudaFuncSetAttribute(lstm_scan,      cudaFuncAttributeMaxDynamicSharedMemorySize, S_SMEM);

    prep_kernel<<<(NG * 64 + 255) / 256, 256>>>(w_ih, w_hh, b_ih, b_hh);
    xg_gemm_kernel<<<ROWS / 128, 512, G_SMEM>>>(x, w_in, b_in);
    lstm_scan<<<NBLK, 512, S_SMEM>>>(w_out, b_out, out);
}